// round 11
// baseline (speedup 1.0000x reference)
#include <cuda_runtime.h>
#include <cuda_bf16.h>
#include <math.h>

// PointNetKAN on GB300, round 9: wider warp tiles (64x64) on the heavy layers.
//  - prep: BN+tanh -> {t,t^2,t^3} -> bf16 hi/lo planes (k-major, gmem)
//  - GEMM: cp.async -> ldmatrix.x4.trans -> 3-pass mma.m16n8k16 (fp32 accum)
//  - L5/L6/L7 use CTA tile 128x256 (warp 64x64): mma:ldsm 6:1, fewer A re-reads
//  - fused per-channel BN stats (+max) epilogue; P0 + broadcast-gf folded to biases

#define NPTS 32768
#define EPSV 1e-5f

typedef unsigned long long u64;
typedef unsigned int u32;

// ---------------- scratch ----------------
__device__ __align__(16) float g_bufA[32u * 1024u * 1024u];
__device__ __align__(16) float g_bufB[32u * 512u * 1024u];
__device__ __align__(16) float g_bufT[32u * 128u * 1024u];   // final-layer tanh input
__device__ __align__(16) float g_y2[32u * 64u * 1024u];      // raw L2 out
__device__ __align__(16) __nv_bfloat16 g_Phi[50331648];      // 32*1536*1024
__device__ __align__(16) __nv_bfloat16 g_Plo[50331648];
__device__ __align__(16) __nv_bfloat16 g_P2hi[6291456];      // 32*192*1024 (t2 powers)
__device__ __align__(16) __nv_bfloat16 g_P2lo[6291456];
__device__ __align__(16) __nv_bfloat16 g_Whi[1100000];
__device__ __align__(16) __nv_bfloat16 g_Wlo[1100000];
__device__ double g_dsum[10 * 1024];
__device__ double g_dss[10 * 1024];
__device__ u32 g_maxkey[32 * 1024];
__device__ __align__(16) float g_gpoly[32 * 1024 * 4];
__device__ float g_bias6[32 * 512];
__device__ float g_cbias[9 * 1024];

// ---------------- helpers ----------------
__device__ __forceinline__ u32 fkey(float f) {
    u32 u = __float_as_uint(f);
    return (u & 0x80000000u) ? ~u : (u | 0x80000000u);
}
__device__ __forceinline__ float finv(u32 k) {
    u32 u = (k & 0x80000000u) ? (k ^ 0x80000000u) : ~k;
    return __uint_as_float(u);
}
__device__ __forceinline__ float ftanh(float x) {
    float ax = fminf(fabsf(x), 15.0f);
    float e = __expf(2.0f * ax);
    float t = __fdividef(e - 1.0f, e + 1.0f);
    return copysignf(t, x);
}
__device__ __forceinline__ void jacobi3(float t, float& p1, float& p2, float& p3) {
    p1 = 2.0f * t;
    p2 = 3.75f * t * t - 0.75f;
    p3 = (56.0f / 30.0f) * t * p2 - 0.8f * p1;
}
__device__ __forceinline__ u32 smem_u32(const void* p) {
    u32 a;
    asm("{ .reg .u64 t; cvta.to.shared.u64 t, %1; cvt.u32.u64 %0, t; }" : "=r"(a) : "l"(p));
    return a;
}
__device__ __forceinline__ void cpa16(u32 dst, const void* src) {
    asm volatile("cp.async.cg.shared.global [%0], [%1], 16;" :: "r"(dst), "l"(src) : "memory");
}
__device__ __forceinline__ void ldsm4t(u32* r, u32 addr) {
    asm volatile("ldmatrix.sync.aligned.m8n8.x4.trans.shared.b16 {%0,%1,%2,%3}, [%4];"
                 : "=r"(r[0]), "=r"(r[1]), "=r"(r[2]), "=r"(r[3]) : "r"(addr));
}
__device__ __forceinline__ void mma_bf16(float* c, const u32* a, u32 b0, u32 b1) {
    asm volatile(
        "mma.sync.aligned.m16n8k16.row.col.f32.bf16.bf16.f32 "
        "{%0,%1,%2,%3}, {%4,%5,%6,%7}, {%8,%9}, {%0,%1,%2,%3};"
        : "+f"(c[0]), "+f"(c[1]), "+f"(c[2]), "+f"(c[3])
        : "r"(a[0]), "r"(a[1]), "r"(a[2]), "r"(a[3]), "r"(b0), "r"(b1));
}
__device__ __forceinline__ u32 packbf(float a, float b) {
    __nv_bfloat16 ha = __float2bfloat16(a), hb = __float2bfloat16(b);
    return ((u32)__bfloat16_as_ushort(hb) << 16) | __bfloat16_as_ushort(ha);
}

// ---------------- GEMM: cp.async + trans-ldmatrix + 3-pass mma ----------------
// A planes: Phi/Plo [b][KTOT][1024] bf16 (k-major). B: Whi/Wlo [k][COUT] bf16.
// out: (32, COUT, 1024) fp32 raw; per-channel stats (+max) via atomics.
template <int CIN, int COUT, int TO, bool DOMAX>
__global__ __launch_bounds__(256) void kan_bf(
    const __nv_bfloat16* __restrict__ Phi, const __nv_bfloat16* __restrict__ Plo,
    const __nv_bfloat16* __restrict__ Whi, const __nv_bfloat16* __restrict__ Wlo,
    const float* __restrict__ cbias, const float* __restrict__ bias,
    float* __restrict__ out, double* __restrict__ dsum, double* __restrict__ dss,
    u32* __restrict__ maxkey) {
    constexpr int KTOT = 3 * CIN;
    constexpr int NCH = (KTOT + 31) / 32;
    constexpr int ASTR = 272;                 // bytes per A smem row (128 pts + pad)
    constexpr int BSTR = TO * 2 + 16;         // bytes per B smem row
    constexpr int APL = 32 * ASTR;            // one A plane
    constexpr int BPL = 32 * BSTR;
    constexpr int BUFB = 2 * APL + 2 * BPL;   // one buffer set (Ahi,Alo,Bhi,Blo)
    constexpr int WN = TO / 4;                // warp n-extent (32 or 64)
    constexpr int NT = WN / 8;                // n8 tiles per warp (4 or 8)
    constexpr int NG = NT / 2;                // n16 ldsm groups per warp

    extern __shared__ __align__(16) char smem[];
    const u32 sb = smem_u32(smem);
    const int tid = threadIdx.x;
    const int lane = tid & 31, wid = tid >> 5;
    const int g = lane >> 2, tg = lane & 3;
    const int wm = wid & 1, wn = wid >> 1;
    const int b = blockIdx.x >> 3;
    const int pbase = (blockIdx.x & 7) * 128;
    const int o0 = blockIdx.y * TO;

    float acc[4][NT][4];
#pragma unroll
    for (int mt = 0; mt < 4; mt++)
#pragma unroll
        for (int nt = 0; nt < NT; nt++)
#pragma unroll
            for (int r = 0; r < 4; r++) acc[mt][nt][r] = 0.0f;

    // zero k-padding rows (L1 only: KTOT=6)
    if (KTOT & 31) {
        for (int e = tid; e < (32 - KTOT) * (ASTR / 4); e += 256) {
            int r = e / (ASTR / 4), wd = e % (ASTR / 4);
            *(u32*)(smem + (KTOT + r) * ASTR + wd * 4) = 0;
            *(u32*)(smem + APL + (KTOT + r) * ASTR + wd * 4) = 0;
        }
    }

    auto load_chunk = [&](int ch, int buf) {
        const int kb = ch << 5;
        const u32 base = sb + buf * BUFB;
#pragma unroll
        for (int j = 0; j < 2; ++j) {  // A: 512 16B-segs per plane
            int s = tid + (j << 8);
            int row = s >> 4, c16 = (s & 15) << 4;
            int k = kb + row;
            if ((KTOT & 31) == 0 || k < KTOT) {
                u32 dst = base + row * ASTR + c16;
                size_t gel = (((size_t)(b * KTOT + k)) << 10) + pbase;
                cpa16(dst, (const char*)(Phi + gel) + c16);
                cpa16(dst + APL, (const char*)(Plo + gel) + c16);
            }
        }
        constexpr int BS = 32 * (TO / 8);
#pragma unroll
        for (int j = 0; j < BS / 256; ++j) {
            int s = tid + (j << 8);
            int row = s / (TO / 8), c16 = (s % (TO / 8)) << 4;
            int k = kb + row;
            u32 dst = base + 2 * APL + row * BSTR + c16;
            size_t gel = (size_t)k * COUT + o0;
            cpa16(dst, (const char*)(Whi + gel) + c16);
            cpa16(dst + BPL, (const char*)(Wlo + gel) + c16);
        }
    };

    // lane-dependent ldmatrix offsets
    const u32 a_lofs = ((lane & 7) + ((lane >> 4) << 3)) * ASTR + (((lane >> 3) & 1) << 4);
    const u32 b_lofs = ((lane & 7) + (((lane >> 3) & 1) << 3)) * BSTR + ((lane >> 4) << 4);

    load_chunk(0, 0);
    asm volatile("cp.async.commit_group;" ::: "memory");

    for (int ch = 0; ch < NCH; ++ch) {
        const int buf = ch & 1;
        if (ch + 1 < NCH) {
            load_chunk(ch + 1, buf ^ 1);
            asm volatile("cp.async.commit_group;" ::: "memory");
            asm volatile("cp.async.wait_group 1;" ::: "memory");
        } else {
            asm volatile("cp.async.wait_group 0;" ::: "memory");
        }
        __syncthreads();

        const u32 ab = sb + buf * BUFB;
        const u32 bb = ab + 2 * APL;
#pragma unroll
        for (int ks = 0; ks < 2; ++ks) {
            u32 ah[16], al[16];
#pragma unroll
            for (int mt = 0; mt < 4; mt++) {
                u32 ad = ab + ks * (16 * ASTR) + a_lofs + (wm * 64 + mt * 16) * 2;
                ldsm4t(&ah[4 * mt], ad);
                ldsm4t(&al[4 * mt], ad + APL);
            }
            // stream B n16-groups: only 8 B regs live at a time
#pragma unroll
            for (int ng = 0; ng < NG; ng++) {
                u32 bh[4], bl[4];
                u32 bd = bb + ks * (16 * BSTR) + b_lofs + (wn * WN + ng * 16) * 2;
                ldsm4t(bh, bd);
                ldsm4t(bl, bd + BPL);
#pragma unroll
                for (int mt = 0; mt < 4; mt++)
#pragma unroll
                    for (int h = 0; h < 2; h++) {
                        float* c = acc[mt][2 * ng + h];
                        mma_bf16(c, &ah[4 * mt], bh[2 * h], bh[2 * h + 1]);
                        mma_bf16(c, &ah[4 * mt], bl[2 * h], bl[2 * h + 1]);
                        mma_bf16(c, &al[4 * mt], bh[2 * h], bh[2 * h + 1]);
                    }
            }
        }
        if (ch + 1 < NCH) __syncthreads();
    }

    // ---- epilogue: bias, stores, fused stats (+max) ----
#pragma unroll
    for (int nt = 0; nt < NT; nt++) {
        const int o = o0 + wn * WN + nt * 8 + 2 * tg;
        float add0 = cbias[o] + (bias ? bias[b * COUT + o] : 0.0f);
        float add1 = cbias[o + 1] + (bias ? bias[b * COUT + o + 1] : 0.0f);
        float s0 = 0, ss0 = 0, s1 = 0, ss1 = 0;
        float mx0 = -3.4e38f, mx1 = -3.4e38f;
#pragma unroll
        for (int mt = 0; mt < 4; mt++) {
            int pt = pbase + wm * 64 + mt * 16 + g;
            float v00 = acc[mt][nt][0] + add0, v01 = acc[mt][nt][1] + add1;
            float v10 = acc[mt][nt][2] + add0, v11 = acc[mt][nt][3] + add1;
            float* r0 = out + (((size_t)(b * COUT + o)) << 10) + pt;
            float* r1 = out + (((size_t)(b * COUT + o + 1)) << 10) + pt;
            r0[0] = v00; r0[8] = v10; r1[0] = v01; r1[8] = v11;
            s0 += v00 + v10; ss0 += v00 * v00 + v10 * v10;
            s1 += v01 + v11; ss1 += v01 * v01 + v11 * v11;
            if (DOMAX) { mx0 = fmaxf(mx0, fmaxf(v00, v10)); mx1 = fmaxf(mx1, fmaxf(v01, v11)); }
        }
#pragma unroll
        for (int off = 4; off < 32; off <<= 1) {
            s0 += __shfl_xor_sync(0xffffffffu, s0, off);
            ss0 += __shfl_xor_sync(0xffffffffu, ss0, off);
            s1 += __shfl_xor_sync(0xffffffffu, s1, off);
            ss1 += __shfl_xor_sync(0xffffffffu, ss1, off);
            if (DOMAX) {
                mx0 = fmaxf(mx0, __shfl_xor_sync(0xffffffffu, mx0, off));
                mx1 = fmaxf(mx1, __shfl_xor_sync(0xffffffffu, mx1, off));
            }
        }
        if (lane < 4) {
            atomicAdd(&dsum[o], (double)s0);
            atomicAdd(&dss[o], (double)ss0);
            atomicAdd(&dsum[o + 1], (double)s1);
            atomicAdd(&dss[o + 1], (double)ss1);
            if (DOMAX) {
                atomicMax(&maxkey[b * 1024 + o], fkey(mx0));
                atomicMax(&maxkey[b * 1024 + o + 1], fkey(mx1));
            }
        }
    }
}

// ---------------- prep: BN + tanh -> power planes (bf16 hi/lo, k-major) ----------------
template <bool TOUT>
__global__ void prep_kernel(const float* __restrict__ in, const double* __restrict__ dsum,
                            const double* __restrict__ dss, int C,
                            __nv_bfloat16* __restrict__ Phi, __nv_bfloat16* __restrict__ Plo,
                            float* __restrict__ Tout) {
    int bi = blockIdx.x;
    int c = bi % C, b = bi / C;
    float m = 0.0f, r = 1.0f;
    if (dsum) {
        double mm = dsum[c] * (1.0 / NPTS);
        double var = fma(-mm, mm, dss[c] * (1.0 / NPTS));
        m = (float)mm;
        r = rsqrtf((float)var + EPSV);
    }
    int i = threadIdx.x;
    float4 v = ((const float4*)(in + ((size_t)bi << 10)))[i];
    float t0 = ftanh((v.x - m) * r), t1 = ftanh((v.y - m) * r);
    float t2 = ftanh((v.z - m) * r), t3 = ftanh((v.w - m) * r);
    if (TOUT) ((float4*)(Tout + ((size_t)bi << 10)))[i] = make_float4(t0, t1, t2, t3);
    size_t row = ((size_t)(b * 3 * C + 3 * c)) << 10;
    float p0 = t0, p1 = t1, p2 = t2, p3 = t3;
#pragma unroll
    for (int rr = 0; rr < 3; ++rr) {
        if (rr) { p0 *= t0; p1 *= t1; p2 *= t2; p3 *= t3; }
        __nv_bfloat16 h0 = __float2bfloat16(p0), h1 = __float2bfloat16(p1);
        __nv_bfloat16 h2 = __float2bfloat16(p2), h3 = __float2bfloat16(p3);
        uint2 hv, lv;
        hv.x = ((u32)__bfloat16_as_ushort(h1) << 16) | __bfloat16_as_ushort(h0);
        hv.y = ((u32)__bfloat16_as_ushort(h3) << 16) | __bfloat16_as_ushort(h2);
        lv.x = packbf(p0 - __bfloat162float(h0), p1 - __bfloat162float(h1));
        lv.y = packbf(p2 - __bfloat162float(h2), p3 - __bfloat162float(h3));
        ((uint2*)(Phi + row + ((size_t)rr << 10)))[i] = hv;
        ((uint2*)(Plo + row + ((size_t)rr << 10)))[i] = lv;
    }
}

// ---------------- weight prep: transformed basis, k-major, zero-padded ----------------
struct WPArgs { const float* w[9]; int cin[9]; int cout[9]; long long off[9]; };
__global__ void wprep_kernel(WPArgs a, __nv_bfloat16* __restrict__ Whi,
                             __nv_bfloat16* __restrict__ Wlo) {
    int l = blockIdx.y;
    int CO = a.cout[l];
    int KP = ((3 * a.cin[l] + 31) / 32) * 32;
    int total = KP * CO;
    int idx = blockIdx.x * 256 + threadIdx.x;
    if (idx >= total) return;
    int k = idx / CO, o = idx - k * CO;
    float v = 0.0f;
    if (k < 3 * a.cin[l]) {
        int c = k / 3, r = k - 3 * c;
        const float* p = a.w[l] + (((size_t)c * CO + o) << 2);
        v = (r == 0) ? (2.0f * p[1] - 3.0f * p[3]) : ((r == 1) ? 3.75f * p[2] : 7.0f * p[3]);
    }
    __nv_bfloat16 h = __float2bfloat16(v);
    Whi[a.off[l] + idx] = h;
    Wlo[a.off[l] + idx] = __float2bfloat16(v - __bfloat162float(h));
}

// ---------------- per-layer constant biases: sum_c (w0 - 0.75*w2) ----------------
struct CBArgs { const float* w[9]; int cin[9]; int cout[9]; };
__global__ void cbias_all_kernel(CBArgs a, float* __restrict__ cb) {
    int l = blockIdx.y;
    int o = blockIdx.x * 256 + threadIdx.x;
    if (o >= a.cout[l]) return;
    const float* w = a.w[l];
    int CO = a.cout[l];
    float s = 0.0f;
    for (int c = 0; c < a.cin[l]; c++) {
        const float* p = &w[((size_t)c * CO + o) * 4];
        s += p[0] - 0.75f * p[2];
    }
    cb[l * 1024 + o] = s;
}

// ---------------- BN + tanh (fp32 out; final-layer input) ----------------
__global__ void tanh_bn_kernel(const float* __restrict__ in, const double* __restrict__ dsum,
                               const double* __restrict__ dss, int C, float* __restrict__ out) {
    int c = blockIdx.x % C;
    double mm = dsum[c] * (1.0 / NPTS);
    double var = fma(-mm, mm, dss[c] * (1.0 / NPTS));
    float m = (float)mm;
    float r = rsqrtf((float)var + EPSV);
    const float4* ip = (const float4*)(in + (size_t)blockIdx.x * 1024);
    float4 v = ip[threadIdx.x];
    v.x = ftanh((v.x - m) * r);
    v.y = ftanh((v.y - m) * r);
    v.z = ftanh((v.z - m) * r);
    v.w = ftanh((v.w - m) * r);
    ((float4*)(out + (size_t)blockIdx.x * 1024))[threadIdx.x] = v;
}

// ---------------- polys of normalized global feature ----------------
__global__ void gpoly_kernel(const u32* __restrict__ mk, const double* __restrict__ dsum,
                             const double* __restrict__ dss, float* __restrict__ gp) {
    int i = blockIdx.x * 256 + threadIdx.x;
    int c = i & 1023;
    double mm = dsum[c] * (1.0 / NPTS);
    double var = fma(-mm, mm, dss[c] * (1.0 / NPTS));
    float r = rsqrtf((float)var + EPSV);
    float t = ftanh((finv(mk[i]) - (float)mm) * r);
    float p1, p2, p3;
    jacobi3(t, p1, p2, p3);
    ((float4*)gp)[i] = make_float4(1.0f, p1, p2, p3);
}

// ---------------- layer-6 bias from gf rows of w6 (original basis) ----------------
__global__ void bias6_kernel(const float* __restrict__ gp, const float* __restrict__ w6g,
                             float* __restrict__ bias) {
    int b = blockIdx.x;
    int o = blockIdx.y * 64 + (threadIdx.x & 63);
    int js = threadIdx.x >> 6;
    const float4* g4 = (const float4*)(gp + (size_t)b * 4096);
    float acc = 0.0f;
    for (int j = js * 256; j < js * 256 + 256; j++) {
        float4 g = g4[j];
        float4 wv = *(const float4*)&w6g[((size_t)j * 512 + o) * 4];
        acc += g.x * wv.x + g.y * wv.y + g.z * wv.z + g.w * wv.w;
    }
    __shared__ float sh[256];
    sh[threadIdx.x] = acc;
    __syncthreads();
    if (threadIdx.x < 64)
        bias[b * 512 + o] = sh[threadIdx.x] + sh[threadIdx.x + 64] +
                            sh[threadIdx.x + 128] + sh[threadIdx.x + 192];
}

// ---------------- final layer: 128 -> 3 (fp32) ----------------
__global__ void final_kernel(const float* __restrict__ tin, const float* __restrict__ w,
                             float* __restrict__ out) {
    __shared__ float ws[128 * 12];
    for (int e = threadIdx.x; e < 1536; e += 256) ws[e] = w[e];
    __syncthreads();
    int gidx = blockIdx.x * 256 + threadIdx.x;
    int b = gidx >> 10, n = gidx & 1023;
    float a0 = 0.0f, a1 = 0.0f, a2 = 0.0f;
    for (int c = 0; c < 128; c++) {
        float t = tin[((size_t)(b * 128 + c)) * 1024 + n];
        float p1, p2, p3;
        jacobi3(t, p1, p2, p3);
        const float* wc = &ws[c * 12];
        a0 += wc[0] + p1 * wc[1] + p2 * wc[2] + p3 * wc[3];
        a1 += wc[4] + p1 * wc[5] + p2 * wc[6] + p3 * wc[7];
        a2 += wc[8] + p1 * wc[9] + p2 * wc[10] + p3 * wc[11];
    }
    out[((size_t)(b * 3 + 0)) * 1024 + n] = a0;
    out[((size_t)(b * 3 + 1)) * 1024 + n] = a1;
    out[((size_t)(b * 3 + 2)) * 1024 + n] = a2;
}

extern "C" void kernel_launch(void* const* d_in, const int* in_sizes, int n_in,
                              void* d_out, int out_size) {
    const float* x = (const float*)d_in[0];
    const float* w[10];
    for (int i = 0; i < 10; i++) w[i] = (const float*)d_in[i + 1];

    float *bufA, *bufB, *bufT, *y2, *gp, *b6, *cb;
    __nv_bfloat16 *Phi, *Plo, *P2hi, *P2lo, *Whi, *Wlo;
    double *dsum, *dss;
    u32* mk;
    cudaGetSymbolAddress((void**)&bufA, g_bufA);
    cudaGetSymbolAddress((void**)&bufB, g_bufB);
    cudaGetSymbolAddress((void**)&bufT, g_bufT);
    cudaGetSymbolAddress((void**)&y2, g_y2);
    cudaGetSymbolAddress((void**)&Phi, g_Phi);
    cudaGetSymbolAddress((void**)&Plo, g_Plo);
    cudaGetSymbolAddress((void**)&P2hi, g_P2hi);
    cudaGetSymbolAddress((void**)&P2lo, g_P2lo);
    cudaGetSymbolAddress((void**)&Whi, g_Whi);
    cudaGetSymbolAddress((void**)&Wlo, g_Wlo);
    cudaGetSymbolAddress((void**)&dsum, g_dsum);
    cudaGetSymbolAddress((void**)&dss, g_dss);
    cudaGetSymbolAddress((void**)&mk, g_maxkey);
    cudaGetSymbolAddress((void**)&gp, g_gpoly);
    cudaGetSymbolAddress((void**)&b6, g_bias6);
    cudaGetSymbolAddress((void**)&cb, g_cbias);

    cudaMemsetAsync(dsum, 0, 10 * 1024 * sizeof(double));
    cudaMemsetAsync(dss, 0, 10 * 1024 * sizeof(double));
    cudaMemsetAsync(mk, 0, 32 * 1024 * sizeof(u32));

    const int cins[9] = {2, 64, 64, 64, 128, 64, 512, 256, 128};
    const int couts[9] = {64, 64, 64, 128, 1024, 512, 256, 128, 128};
    long long offs[9];
    long long acc = 0;
    for (int i = 0; i < 9; i++) {
        offs[i] = acc;
        long long kp = ((3 * cins[i] + 31) / 32) * 32;
        acc += kp * couts[i];
    }

    CBArgs cba;
    WPArgs wpa;
    for (int i = 0; i < 9; i++) {
        cba.w[i] = w[i]; cba.cin[i] = cins[i]; cba.cout[i] = couts[i];
        wpa.w[i] = w[i]; wpa.cin[i] = cins[i]; wpa.cout[i] = couts[i]; wpa.off[i] = offs[i];
    }
    cbias_all_kernel<<<dim3(4, 9), 256>>>(cba, cb);
    wprep_kernel<<<dim3(1536, 9), 256>>>(wpa, Whi, Wlo);

    const int SM64 = 53248, SM128 = 69632, SM256 = 102400;
    cudaFuncSetAttribute(kan_bf<2, 64, 64, false>, cudaFuncAttributeMaxDynamicSharedMemorySize, SM64);
    cudaFuncSetAttribute(kan_bf<64, 64, 64, false>, cudaFuncAttributeMaxDynamicSharedMemorySize, SM64);
    cudaFuncSetAttribute(kan_bf<64, 128, 128, false>, cudaFuncAttributeMaxDynamicSharedMemorySize, SM128);
    cudaFuncSetAttribute(kan_bf<128, 1024, 256, true>, cudaFuncAttributeMaxDynamicSharedMemorySize, SM256);
    cudaFuncSetAttribute(kan_bf<64, 512, 256, false>, cudaFuncAttributeMaxDynamicSharedMemorySize, SM256);
    cudaFuncSetAttribute(kan_bf<512, 256, 256, false>, cudaFuncAttributeMaxDynamicSharedMemorySize, SM256);
    cudaFuncSetAttribute(kan_bf<256, 128, 128, false>, cudaFuncAttributeMaxDynamicSharedMemorySize, SM128);
    cudaFuncSetAttribute(kan_bf<128, 128, 128, false>, cudaFuncAttributeMaxDynamicSharedMemorySize, SM128);

    const int GX = 256;  // 32 batches x 8 tiles of 128 points

    // L1: 2 -> 64
    prep_kernel<false><<<32 * 2, 256>>>(x, nullptr, nullptr, 2, Phi, Plo, nullptr);
    kan_bf<2, 64, 64, false><<<dim3(GX, 1), 256, SM64>>>(Phi, Plo, Whi + offs[0], Wlo + offs[0],
                                                         cb + 0, nullptr, bufA, dsum + 0, dss + 0, nullptr);
    // L2: 64 -> 64 (raw out kept as local feature)
    prep_kernel<false><<<32 * 64, 256>>>(bufA, dsum + 0, dss + 0, 64, Phi, Plo, nullptr);
    kan_bf<64, 64, 64, false><<<dim3(GX, 1), 256, SM64>>>(Phi, Plo, Whi + offs[1], Wlo + offs[1],
                                                          cb + 1024, nullptr, y2, dsum + 1024, dss + 1024, nullptr);
    // t2 power planes (reused by L3 and L6)
    prep_kernel<false><<<32 * 64, 256>>>(y2, dsum + 1024, dss + 1024, 64, P2hi, P2lo, nullptr);
    // L3: 64 -> 64
    kan_bf<64, 64, 64, false><<<dim3(GX, 1), 256, SM64>>>(P2hi, P2lo, Whi + offs[2], Wlo + offs[2],
                                                          cb + 2048, nullptr, bufA, dsum + 2048, dss + 2048, nullptr);
    // L4: 64 -> 128
    prep_kernel<false><<<32 * 64, 256>>>(bufA, dsum + 2048, dss + 2048, 64, Phi, Plo, nullptr);
    kan_bf<64, 128, 128, false><<<dim3(GX, 1), 256, SM128>>>(Phi, Plo, Whi + offs[3], Wlo + offs[3],
                                                             cb + 3072, nullptr, bufB, dsum + 3072, dss + 3072, nullptr);
    // L5: 128 -> 1024 (fused maxpool), 128x256 CTA tiles
    prep_kernel<false><<<32 * 128, 256>>>(bufB, dsum + 3072, dss + 3072, 128, Phi, Plo, nullptr);
    kan_bf<128, 1024, 256, true><<<dim3(GX, 4), 256, SM256>>>(Phi, Plo, Whi + offs[4], Wlo + offs[4],
                                                              cb + 4096, nullptr, bufA, dsum + 4096, dss + 4096, mk);
    // global feature path
    gpoly_kernel<<<128, 256>>>(mk, dsum + 4096, dss + 4096, gp);
    bias6_kernel<<<dim3(32, 8), 256>>>(gp, w[5] + (size_t)64 * 512 * 4, b6);
    // L6: 64 local channels + gf folded bias -> 512, 128x256 tiles
    kan_bf<64, 512, 256, false><<<dim3(GX, 2), 256, SM256>>>(P2hi, P2lo, Whi + offs[5], Wlo + offs[5],
                                                             cb + 5120, b6, bufB, dsum + 5120, dss + 5120, nullptr);
    // L7: 512 -> 256, 128x256 tiles
    prep_kernel<false><<<32 * 512, 256>>>(bufB, dsum + 5120, dss + 5120, 512, Phi, Plo, nullptr);
    kan_bf<512, 256, 256, false><<<dim3(GX, 1), 256, SM256>>>(Phi, Plo, Whi + offs[6], Wlo + offs[6],
                                                              cb + 6144, nullptr, bufA, dsum + 6144, dss + 6144, nullptr);
    // L8: 256 -> 128
    prep_kernel<false><<<32 * 256, 256>>>(bufA, dsum + 6144, dss + 6144, 256, Phi, Plo, nullptr);
    kan_bf<256, 128, 128, false><<<dim3(GX, 1), 256, SM128>>>(Phi, Plo, Whi + offs[7], Wlo + offs[7],
                                                              cb + 7168, nullptr, bufB, dsum + 7168, dss + 7168, nullptr);
    // L9: 128 -> 128
    prep_kernel<false><<<32 * 128, 256>>>(bufB, dsum + 7168, dss + 7168, 128, Phi, Plo, nullptr);
    kan_bf<128, 128, 128, false><<<dim3(GX, 1), 256, SM128>>>(Phi, Plo, Whi + offs[8], Wlo + offs[8],
                                                              cb + 8192, nullptr, bufA, dsum + 8192, dss + 8192, nullptr);
    // L10: 128 -> 3 (no BN after)
    tanh_bn_kernel<<<32 * 128, 256>>>(bufA, dsum + 8192, dss + 8192, 128, bufT);
    final_kernel<<<128, 256>>>(bufT, w[9], (float*)d_out);
}

// round 12
// speedup vs baseline: 1.0616x; 1.0616x over previous
#include <cuda_runtime.h>
#include <cuda_bf16.h>
#include <math.h>

// PointNetKAN on GB300, round 12: fused register-space transform + bf16 3-pass mma.
//  - GEMM computes BN+tanh+{t,t^2,t^3}+bf16 hi/lo split inline (regs -> STS.128),
//    overlapped with the mma phase; raw fp32 input LDG-prefetched one chunk ahead.
//  - chunk = 48 logical k (16 channels): no /3 indexing, 3 mma k-steps.
//  - no prep kernels, no plane arrays (saves ~730MB DRAM traffic + 9 launches).
//  - weights pre-split bf16 hi/lo k-major (48-padded); 3-pass mma m16n8k16.
//  - fused per-channel BN stats (+max) epilogue; P0 + broadcast-gf folded to biases.

#define NPTS 32768
#define EPSV 1e-5f

typedef unsigned long long u64;
typedef unsigned int u32;

// ---------------- scratch ----------------
__device__ __align__(16) float g_bufA[32u * 1024u * 1024u];
__device__ __align__(16) float g_bufB[32u * 512u * 1024u];
__device__ __align__(16) float g_bufT[32u * 128u * 1024u];   // final-layer tanh input
__device__ __align__(16) float g_y2[32u * 64u * 1024u];      // raw L2 out (L3 + L6 input)
__device__ __align__(16) __nv_bfloat16 g_Whi[1200000];
__device__ __align__(16) __nv_bfloat16 g_Wlo[1200000];
__device__ double g_dsum[10 * 1024];
__device__ double g_dss[10 * 1024];
__device__ u32 g_maxkey[32 * 1024];
__device__ __align__(16) float g_gpoly[32 * 1024 * 4];
__device__ float g_bias6[32 * 512];
__device__ float g_cbias[9 * 1024];

// ---------------- helpers ----------------
__device__ __forceinline__ u32 fkey(float f) {
    u32 u = __float_as_uint(f);
    return (u & 0x80000000u) ? ~u : (u | 0x80000000u);
}
__device__ __forceinline__ float finv(u32 k) {
    u32 u = (k & 0x80000000u) ? (k ^ 0x80000000u) : ~k;
    return __uint_as_float(u);
}
__device__ __forceinline__ float ftanh(float x) {
    float ax = fminf(fabsf(x), 15.0f);
    float e = __expf(2.0f * ax);
    float t = __fdividef(e - 1.0f, e + 1.0f);
    return copysignf(t, x);
}
__device__ __forceinline__ void jacobi3(float t, float& p1, float& p2, float& p3) {
    p1 = 2.0f * t;
    p2 = 3.75f * t * t - 0.75f;
    p3 = (56.0f / 30.0f) * t * p2 - 0.8f * p1;
}
__device__ __forceinline__ u32 smem_u32(const void* p) {
    u32 a;
    asm("{ .reg .u64 t; cvta.to.shared.u64 t, %1; cvt.u32.u64 %0, t; }" : "=r"(a) : "l"(p));
    return a;
}
__device__ __forceinline__ void cpa16(u32 dst, const void* src) {
    asm volatile("cp.async.cg.shared.global [%0], [%1], 16;" :: "r"(dst), "l"(src) : "memory");
}
__device__ __forceinline__ void ldsm4t(u32* r, u32 addr) {
    asm volatile("ldmatrix.sync.aligned.m8n8.x4.trans.shared.b16 {%0,%1,%2,%3}, [%4];"
                 : "=r"(r[0]), "=r"(r[1]), "=r"(r[2]), "=r"(r[3]) : "r"(addr));
}
__device__ __forceinline__ void mma_bf16(float* c, const u32* a, u32 b0, u32 b1) {
    asm volatile(
        "mma.sync.aligned.m16n8k16.row.col.f32.bf16.bf16.f32 "
        "{%0,%1,%2,%3}, {%4,%5,%6,%7}, {%8,%9}, {%0,%1,%2,%3};"
        : "+f"(c[0]), "+f"(c[1]), "+f"(c[2]), "+f"(c[3])
        : "r"(a[0]), "r"(a[1]), "r"(a[2]), "r"(a[3]), "r"(b0), "r"(b1));
}
__device__ __forceinline__ u32 packbf(float a, float b) {
    __nv_bfloat16 ha = __float2bfloat16(a), hb = __float2bfloat16(b);
    return ((u32)__bfloat16_as_ushort(hb) << 16) | __bfloat16_as_ushort(ha);
}
__device__ __forceinline__ void split2(float x, float y, u32& hi, u32& lo) {
    __nv_bfloat16 hx = __float2bfloat16(x), hy = __float2bfloat16(y);
    hi = ((u32)__bfloat16_as_ushort(hy) << 16) | __bfloat16_as_ushort(hx);
    lo = packbf(x - __bfloat162float(hx), y - __bfloat162float(hy));
}

// ---------------- fused-transform bf16 mma KAN GEMM ----------------
// in: (32, CIN, 1024) RAW fp32 (BN inline from dsumIn/dssIn; null -> identity).
// W:  bf16 hi/lo, k-major [KP][COUT], KP padded to multiple of 48.
// out: (32, COUT, 1024) fp32 raw; per-channel stats (+max) via atomics.
template <int CIN, int COUT, int TO, bool DOMAX>
__global__ __launch_bounds__(256, 2) void kan_bf(
    const float* __restrict__ in, const double* __restrict__ dsumIn,
    const double* __restrict__ dssIn,
    const __nv_bfloat16* __restrict__ Whi, const __nv_bfloat16* __restrict__ Wlo,
    const float* __restrict__ cbias, const float* __restrict__ bias,
    float* __restrict__ out, double* __restrict__ dsum, double* __restrict__ dss,
    u32* __restrict__ maxkey) {
    constexpr int KTOT = 3 * CIN;
    constexpr int NCH = (KTOT + 47) / 48;     // 16 channels (48 k) per chunk
    constexpr int ASTR = 272;                 // bytes per A smem row (128 pts + pad)
    constexpr int BSTR = TO * 2 + 16;
    constexpr int APL = 48 * ASTR;            // one A plane (hi or lo)
    constexpr int BPL = 48 * BSTR;
    constexpr int BUFB = 2 * APL + 2 * BPL;
    constexpr int WN = TO / 4;
    constexpr int NT = WN / 8;
    constexpr int NG = NT / 2;
    constexpr int BSEGS = 6 * TO;             // 16B segs per B plane per chunk

    extern __shared__ __align__(16) char smem[];
    const u32 sb = smem_u32(smem);
    const int tid = threadIdx.x;
    const int lane = tid & 31, wid = tid >> 5;
    const int g = lane >> 2, tg = lane & 3;
    const int wm = wid & 1, wn = wid >> 1;
    const int b = blockIdx.x >> 3;
    const int pbase = (blockIdx.x & 7) * 128;
    const int o0 = blockIdx.y * TO;
    const int cg = tid >> 4;                  // channel-in-chunk 0..15
    const int pseg = (tid & 15) << 3;         // 8-point segment base

    float acc[4][NT][4];
#pragma unroll
    for (int mt = 0; mt < 4; mt++)
#pragma unroll
        for (int nt = 0; nt < NT; nt++)
#pragma unroll
            for (int r = 0; r < 4; r++) acc[mt][nt][r] = 0.0f;

    float rv[8];
    auto load_raw = [&](int ch) {
        int c = ch * 16 + cg;
        if (c < CIN) {
            const float4* p =
                (const float4*)(in + (((size_t)(b * CIN + c)) << 10) + pbase + pseg);
            float4 u0 = p[0], u1 = p[1];
            rv[0] = u0.x; rv[1] = u0.y; rv[2] = u0.z; rv[3] = u0.w;
            rv[4] = u1.x; rv[5] = u1.y; rv[6] = u1.z; rv[7] = u1.w;
        }
    };
    auto xform = [&](int ch, int buf) {
        char* ab = smem + buf * BUFB;
        const u32 rowb = (u32)(3 * cg) * ASTR + ((u32)pseg << 1);
        int c = ch * 16 + cg;
        uint4 h1, l1, h2, l2, h3, l3;
        if (c < CIN) {
            float m = 0.0f, r = 1.0f;
            if (dsumIn) {
                double mm = dsumIn[c] * (1.0 / NPTS);
                double var = fma(-mm, mm, dssIn[c] * (1.0 / NPTS));
                m = (float)mm;
                r = rsqrtf((float)var + EPSV);
            }
            float t[8];
#pragma unroll
            for (int j = 0; j < 8; j++) t[j] = ftanh((rv[j] - m) * r);
            u32* H1 = (u32*)&h1; u32* L1 = (u32*)&l1;
            u32* H2 = (u32*)&h2; u32* L2 = (u32*)&l2;
            u32* H3 = (u32*)&h3; u32* L3 = (u32*)&l3;
#pragma unroll
            for (int j = 0; j < 4; j++) {
                float a = t[2 * j], bb = t[2 * j + 1];
                float a2 = a * a, b2 = bb * bb;
                split2(a, bb, H1[j], L1[j]);
                split2(a2, b2, H2[j], L2[j]);
                split2(a2 * a, b2 * bb, H3[j], L3[j]);
            }
        } else {
            h1 = l1 = h2 = l2 = h3 = l3 = make_uint4(0, 0, 0, 0);
        }
        *(uint4*)(ab + rowb) = h1;
        *(uint4*)(ab + rowb + ASTR) = h2;
        *(uint4*)(ab + rowb + 2 * ASTR) = h3;
        *(uint4*)(ab + APL + rowb) = l1;
        *(uint4*)(ab + APL + rowb + ASTR) = l2;
        *(uint4*)(ab + APL + rowb + 2 * ASTR) = l3;
    };
    auto loadB = [&](int ch, int buf) {
        const int kb = ch * 48;
        const u32 base = sb + buf * BUFB + 2 * APL;
        for (int s = tid; s < BSEGS; s += 256) {
            int row = s / (TO / 8), c16 = (s % (TO / 8)) << 4;
            u32 dst = base + row * BSTR + c16;
            size_t gel = (size_t)(kb + row) * COUT + o0;
            cpa16(dst, (const char*)(Whi + gel) + c16);
            cpa16(dst + BPL, (const char*)(Wlo + gel) + c16);
        }
    };

    const u32 a_lofs = ((lane & 7) + ((lane >> 4) << 3)) * ASTR + (((lane >> 3) & 1) << 4);
    const u32 b_lofs = ((lane & 7) + (((lane >> 3) & 1) << 3)) * BSTR + ((lane >> 4) << 4);

    load_raw(0);
    xform(0, 0);
    loadB(0, 0);
    asm volatile("cp.async.commit_group;" ::: "memory");
    if (1 < NCH) load_raw(1);

    for (int ch = 0; ch < NCH; ++ch) {
        const int buf = ch & 1;
        if (ch + 1 < NCH) {
            loadB(ch + 1, buf ^ 1);
            asm volatile("cp.async.commit_group;" ::: "memory");
            asm volatile("cp.async.wait_group 1;" ::: "memory");
        } else {
            asm volatile("cp.async.wait_group 0;" ::: "memory");
        }
        __syncthreads();  // A(ch) + B(ch) ready for all warps

        const u32 ab = sb + buf * BUFB;
        const u32 bb = ab + 2 * APL;
#pragma unroll
        for (int ks = 0; ks < 3; ++ks) {
            u32 ah[16], al[16];
#pragma unroll
            for (int mt = 0; mt < 4; mt++) {
                u32 ad = ab + ks * (16 * ASTR) + a_lofs + (wm * 64 + mt * 16) * 2;
                ldsm4t(&ah[4 * mt], ad);
                ldsm4t(&al[4 * mt], ad + APL);
            }
#pragma unroll
            for (int ng = 0; ng < NG; ng++) {
                u32 bh[4], bl[4];
                u32 bd = bb + ks * (16 * BSTR) + b_lofs + (wn * WN + ng * 16) * 2;
                ldsm4t(bh, bd);
                ldsm4t(bl, bd + BPL);
#pragma unroll
                for (int mt = 0; mt < 4; mt++)
#pragma unroll
                    for (int h = 0; h < 2; h++) {
                        float* c = acc[mt][2 * ng + h];
                        mma_bf16(c, &ah[4 * mt], bh[2 * h], bh[2 * h + 1]);
                        mma_bf16(c, &ah[4 * mt], bl[2 * h], bl[2 * h + 1]);
                        mma_bf16(c, &al[4 * mt], bh[2 * h], bh[2 * h + 1]);
                    }
            }
        }
        if (ch + 1 < NCH) {
            xform(ch + 1, buf ^ 1);           // fill A of next buffer (other plane area)
            if (ch + 2 < NCH) load_raw(ch + 2);
            __syncthreads();                  // protect B(buf) rewrite next iteration
        }
    }

    // ---- epilogue: bias, stores, fused stats (+max) ----
#pragma unroll
    for (int nt = 0; nt < NT; nt++) {
        const int o = o0 + wn * WN + nt * 8 + 2 * tg;
        float add0 = cbias[o] + (bias ? bias[b * COUT + o] : 0.0f);
        float add1 = cbias[o + 1] + (bias ? bias[b * COUT + o + 1] : 0.0f);
        float s0 = 0, ss0 = 0, s1 = 0, ss1 = 0;
        float mx0 = -3.4e38f, mx1 = -3.4e38f;
#pragma unroll
        for (int mt = 0; mt < 4; mt++) {
            int pt = pbase + wm * 64 + mt * 16 + g;
            float v00 = acc[mt][nt][0] + add0, v01 = acc[mt][nt][1] + add1;
            float v10 = acc[mt][nt][2] + add0, v11 = acc[mt][nt][3] + add1;
            float* r0 = out + (((size_t)(b * COUT + o)) << 10) + pt;
            float* r1 = out + (((size_t)(b * COUT + o + 1)) << 10) + pt;
            r0[0] = v00; r0[8] = v10; r1[0] = v01; r1[8] = v11;
            s0 += v00 + v10; ss0 += v00 * v00 + v10 * v10;
            s1 += v01 + v11; ss1 += v01 * v01 + v11 * v11;
            if (DOMAX) { mx0 = fmaxf(mx0, fmaxf(v00, v10)); mx1 = fmaxf(mx1, fmaxf(v01, v11)); }
        }
#pragma unroll
        for (int off = 4; off < 32; off <<= 1) {
            s0 += __shfl_xor_sync(0xffffffffu, s0, off);
            ss0 += __shfl_xor_sync(0xffffffffu, ss0, off);
            s1 += __shfl_xor_sync(0xffffffffu, s1, off);
            ss1 += __shfl_xor_sync(0xffffffffu, ss1, off);
            if (DOMAX) {
                mx0 = fmaxf(mx0, __shfl_xor_sync(0xffffffffu, mx0, off));
                mx1 = fmaxf(mx1, __shfl_xor_sync(0xffffffffu, mx1, off));
            }
        }
        if (lane < 4) {
            atomicAdd(&dsum[o], (double)s0);
            atomicAdd(&dss[o], (double)ss0);
            atomicAdd(&dsum[o + 1], (double)s1);
            atomicAdd(&dss[o + 1], (double)ss1);
            if (DOMAX) {
                atomicMax(&maxkey[b * 1024 + o], fkey(mx0));
                atomicMax(&maxkey[b * 1024 + o + 1], fkey(mx1));
            }
        }
    }
}

// ---------------- weight prep: transformed basis, k-major, 48-padded ----------------
struct WPArgs { const float* w[9]; int cin[9]; int cout[9]; long long off[9]; };
__global__ void wprep_kernel(WPArgs a, __nv_bfloat16* __restrict__ Whi,
                             __nv_bfloat16* __restrict__ Wlo) {
    int l = blockIdx.y;
    int CO = a.cout[l];
    int KP = ((3 * a.cin[l] + 47) / 48) * 48;
    int total = KP * CO;
    int idx = blockIdx.x * 256 + threadIdx.x;
    if (idx >= total) return;
    int k = idx / CO, o = idx - k * CO;
    float v = 0.0f;
    if (k < 3 * a.cin[l]) {
        int c = k / 3, r = k - 3 * c;
        const float* p = a.w[l] + (((size_t)c * CO + o) << 2);
        v = (r == 0) ? (2.0f * p[1] - 3.0f * p[3]) : ((r == 1) ? 3.75f * p[2] : 7.0f * p[3]);
    }
    __nv_bfloat16 h = __float2bfloat16(v);
    Whi[a.off[l] + idx] = h;
    Wlo[a.off[l] + idx] = __float2bfloat16(v - __bfloat162float(h));
}

// ---------------- per-layer constant biases: sum_c (w0 - 0.75*w2) ----------------
struct CBArgs { const float* w[9]; int cin[9]; int cout[9]; };
__global__ void cbias_all_kernel(CBArgs a, float* __restrict__ cb) {
    int l = blockIdx.y;
    int o = blockIdx.x * 256 + threadIdx.x;
    if (o >= a.cout[l]) return;
    const float* w = a.w[l];
    int CO = a.cout[l];
    float s = 0.0f;
    for (int c = 0; c < a.cin[l]; c++) {
        const float* p = &w[((size_t)c * CO + o) * 4];
        s += p[0] - 0.75f * p[2];
    }
    cb[l * 1024 + o] = s;
}

// ---------------- polys of normalized global feature ----------------
__global__ void gpoly_kernel(const u32* __restrict__ mk, const double* __restrict__ dsum,
                             const double* __restrict__ dss, float* __restrict__ gp) {
    int i = blockIdx.x * 256 + threadIdx.x;
    int c = i & 1023;
    double mm = dsum[c] * (1.0 / NPTS);
    double var = fma(-mm, mm, dss[c] * (1.0 / NPTS));
    float r = rsqrtf((float)var + EPSV);
    float t = ftanh((finv(mk[i]) - (float)mm) * r);
    float p1, p2, p3;
    jacobi3(t, p1, p2, p3);
    ((float4*)gp)[i] = make_float4(1.0f, p1, p2, p3);
}

// ---------------- layer-6 bias from gf rows of w6 (original basis) ----------------
__global__ void bias6_kernel(const float* __restrict__ gp, const float* __restrict__ w6g,
                             float* __restrict__ bias) {
    int b = blockIdx.x;
    int o = blockIdx.y * 64 + (threadIdx.x & 63);
    int js = threadIdx.x >> 6;
    const float4* g4 = (const float4*)(gp + (size_t)b * 4096);
    float acc = 0.0f;
    for (int j = js * 256; j < js * 256 + 256; j++) {
        float4 g = g4[j];
        float4 wv = *(const float4*)&w6g[((size_t)j * 512 + o) * 4];
        acc += g.x * wv.x + g.y * wv.y + g.z * wv.z + g.w * wv.w;
    }
    __shared__ float sh[256];
    sh[threadIdx.x] = acc;
    __syncthreads();
    if (threadIdx.x < 64)
        bias[b * 512 + o] = sh[threadIdx.x] + sh[threadIdx.x + 64] +
                            sh[threadIdx.x + 128] + sh[threadIdx.x + 192];
}

// ---------------- BN + tanh (final-layer input) ----------------
__global__ void tanh_bn_kernel(const float* __restrict__ in, const double* __restrict__ dsum,
                               const double* __restrict__ dss, int C, float* __restrict__ out) {
    int c = blockIdx.x % C;
    double mm = dsum[c] * (1.0 / NPTS);
    double var = fma(-mm, mm, dss[c] * (1.0 / NPTS));
    float m = (float)mm;
    float r = rsqrtf((float)var + EPSV);
    const float4* ip = (const float4*)(in + (size_t)blockIdx.x * 1024);
    float4 v = ip[threadIdx.x];
    v.x = ftanh((v.x - m) * r);
    v.y = ftanh((v.y - m) * r);
    v.z = ftanh((v.z - m) * r);
    v.w = ftanh((v.w - m) * r);
    ((float4*)(out + (size_t)blockIdx.x * 1024))[threadIdx.x] = v;
}

// ---------------- final layer: 128 -> 3 (fp32) ----------------
__global__ void final_kernel(const float* __restrict__ tin, const float* __restrict__ w,
                             float* __restrict__ out) {
    __shared__ float ws[128 * 12];
    for (int e = threadIdx.x; e < 1536; e += 256) ws[e] = w[e];
    __syncthreads();
    int gidx = blockIdx.x * 256 + threadIdx.x;
    int b = gidx >> 10, n = gidx & 1023;
    float a0 = 0.0f, a1 = 0.0f, a2 = 0.0f;
    for (int c = 0; c < 128; c++) {
        float t = tin[((size_t)(b * 128 + c)) * 1024 + n];
        float p1, p2, p3;
        jacobi3(t, p1, p2, p3);
        const float* wc = &ws[c * 12];
        a0 += wc[0] + p1 * wc[1] + p2 * wc[2] + p3 * wc[3];
        a1 += wc[4] + p1 * wc[5] + p2 * wc[6] + p3 * wc[7];
        a2 += wc[8] + p1 * wc[9] + p2 * wc[10] + p3 * wc[11];
    }
    out[((size_t)(b * 3 + 0)) * 1024 + n] = a0;
    out[((size_t)(b * 3 + 1)) * 1024 + n] = a1;
    out[((size_t)(b * 3 + 2)) * 1024 + n] = a2;
}

extern "C" void kernel_launch(void* const* d_in, const int* in_sizes, int n_in,
                              void* d_out, int out_size) {
    const float* x = (const float*)d_in[0];
    const float* w[10];
    for (int i = 0; i < 10; i++) w[i] = (const float*)d_in[i + 1];

    float *bufA, *bufB, *bufT, *y2, *gp, *b6, *cb;
    __nv_bfloat16 *Whi, *Wlo;
    double *dsum, *dss;
    u32* mk;
    cudaGetSymbolAddress((void**)&bufA, g_bufA);
    cudaGetSymbolAddress((void**)&bufB, g_bufB);
    cudaGetSymbolAddress((void**)&bufT, g_bufT);
    cudaGetSymbolAddress((void**)&y2, g_y2);
    cudaGetSymbolAddress((void**)&Whi, g_Whi);
    cudaGetSymbolAddress((void**)&Wlo, g_Wlo);
    cudaGetSymbolAddress((void**)&dsum, g_dsum);
    cudaGetSymbolAddress((void**)&dss, g_dss);
    cudaGetSymbolAddress((void**)&mk, g_maxkey);
    cudaGetSymbolAddress((void**)&gp, g_gpoly);
    cudaGetSymbolAddress((void**)&b6, g_bias6);
    cudaGetSymbolAddress((void**)&cb, g_cbias);

    cudaMemsetAsync(dsum, 0, 10 * 1024 * sizeof(double));
    cudaMemsetAsync(dss, 0, 10 * 1024 * sizeof(double));
    cudaMemsetAsync(mk, 0, 32 * 1024 * sizeof(u32));

    const int cins[9] = {2, 64, 64, 64, 128, 64, 512, 256, 128};
    const int couts[9] = {64, 64, 64, 128, 1024, 512, 256, 128, 128};
    long long offs[9];
    long long acc = 0;
    for (int i = 0; i < 9; i++) {
        offs[i] = acc;
        long long kp = ((3 * cins[i] + 47) / 48) * 48;
        acc += kp * couts[i];
    }

    CBArgs cba;
    WPArgs wpa;
    for (int i = 0; i < 9; i++) {
        cba.w[i] = w[i]; cba.cin[i] = cins[i]; cba.cout[i] = couts[i];
        wpa.w[i] = w[i]; wpa.cin[i] = cins[i]; wpa.cout[i] = couts[i]; wpa.off[i] = offs[i];
    }
    cbias_all_kernel<<<dim3(4, 9), 256>>>(cba, cb);
    wprep_kernel<<<dim3(1600, 9), 256>>>(wpa, Whi, Wlo);

    // dynamic smem: BUFB*2 = (2*48*272 + 2*48*(TO*2+16)) * 2
    const int SM64 = 79872, SM128 = 104448;
    cudaFuncSetAttribute(kan_bf<2, 64, 64, false>, cudaFuncAttributeMaxDynamicSharedMemorySize, SM64);
    cudaFuncSetAttribute(kan_bf<64, 64, 64, false>, cudaFuncAttributeMaxDynamicSharedMemorySize, SM64);
    cudaFuncSetAttribute(kan_bf<64, 128, 128, false>, cudaFuncAttributeMaxDynamicSharedMemorySize, SM128);
    cudaFuncSetAttribute(kan_bf<128, 1024, 128, true>, cudaFuncAttributeMaxDynamicSharedMemorySize, SM128);
    cudaFuncSetAttribute(kan_bf<64, 512, 128, false>, cudaFuncAttributeMaxDynamicSharedMemorySize, SM128);
    cudaFuncSetAttribute(kan_bf<512, 256, 128, false>, cudaFuncAttributeMaxDynamicSharedMemorySize, SM128);
    cudaFuncSetAttribute(kan_bf<256, 128, 128, false>, cudaFuncAttributeMaxDynamicSharedMemorySize, SM128);
    cudaFuncSetAttribute(kan_bf<128, 128, 128, false>, cudaFuncAttributeMaxDynamicSharedMemorySize, SM128);

    const int GX = 256;  // 32 batches x 8 tiles of 128 points

    // L1: 2 -> 64 (no input BN)
    kan_bf<2, 64, 64, false><<<dim3(GX, 1), 256, SM64>>>(
        x, nullptr, nullptr, Whi + offs[0], Wlo + offs[0], cb + 0, nullptr,
        bufA, dsum + 0, dss + 0, nullptr);
    // L2: 64 -> 64 (raw out kept as local feature)
    kan_bf<64, 64, 64, false><<<dim3(GX, 1), 256, SM64>>>(
        bufA, dsum + 0, dss + 0, Whi + offs[1], Wlo + offs[1], cb + 1024, nullptr,
        y2, dsum + 1024, dss + 1024, nullptr);
    // L3: 64 -> 64 (reads raw y2, BN inline)
    kan_bf<64, 64, 64, false><<<dim3(GX, 1), 256, SM64>>>(
        y2, dsum + 1024, dss + 1024, Whi + offs[2], Wlo + offs[2], cb + 2048, nullptr,
        bufA, dsum + 2048, dss + 2048, nullptr);
    // L4: 64 -> 128
    kan_bf<64, 128, 128, false><<<dim3(GX, 1), 256, SM128>>>(
        bufA, dsum + 2048, dss + 2048, Whi + offs[3], Wlo + offs[3], cb + 3072, nullptr,
        bufB, dsum + 3072, dss + 3072, nullptr);
    // L5: 128 -> 1024 (fused maxpool)
    kan_bf<128, 1024, 128, true><<<dim3(GX, 8), 256, SM128>>>(
        bufB, dsum + 3072, dss + 3072, Whi + offs[4], Wlo + offs[4], cb + 4096, nullptr,
        bufA, dsum + 4096, dss + 4096, mk);
    // global feature path
    gpoly_kernel<<<128, 256>>>(mk, dsum + 4096, dss + 4096, gp);
    bias6_kernel<<<dim3(32, 8), 256>>>(gp, w[5] + (size_t)64 * 512 * 4, b6);
    // L6: 64 local channels (raw y2) + gf folded bias -> 512
    kan_bf<64, 512, 128, false><<<dim3(GX, 4), 256, SM128>>>(
        y2, dsum + 1024, dss + 1024, Whi + offs[5], Wlo + offs[5], cb + 5120, b6,
        bufB, dsum + 5120, dss + 5120, nullptr);
    // L7: 512 -> 256
    kan_bf<512, 256, 128, false><<<dim3(GX, 2), 256, SM128>>>(
        bufB, dsum + 5120, dss + 5120, Whi + offs[6], Wlo + offs[6], cb + 6144, nullptr,
        bufA, dsum + 6144, dss + 6144, nullptr);
    // L8: 256 -> 128
    kan_bf<256, 128, 128, false><<<dim3(GX, 1), 256, SM128>>>(
        bufA, dsum + 6144, dss + 6144, Whi + offs[7], Wlo + offs[7], cb + 7168, nullptr,
        bufB, dsum + 7168, dss + 7168, nullptr);
    // L9: 128 -> 128
    kan_bf<128, 128, 128, false><<<dim3(GX, 1), 256, SM128>>>(
        bufB, dsum + 7168, dss + 7168, Whi + offs[8], Wlo + offs[8], cb + 8192, nullptr,
        bufA, dsum + 8192, dss + 8192, nullptr);
    // L10: 128 -> 3 (no BN after)
    tanh_bn_kernel<<<32 * 128, 256>>>(bufA, dsum + 8192, dss + 8192, 128, bufT);
    final_kernel<<<128, 256>>>(bufT, w[9], (float*)d_out);
}